// round 3
// baseline (speedup 1.0000x reference)
#include <cuda_runtime.h>
#include <math.h>

// ---------------- problem constants ----------------
constexpr int B_   = 2;
constexpr int S_   = 2048;
constexpr int HID  = 2048;
constexpr int NH   = 16;
constexpr int NKV  = 4;
constexpr int HD   = 128;
constexpr int WINDOW = 512;
constexpr int TOK  = B_ * S_;          // 4096

// ---------------- scratch (device globals; no allocation allowed) ----------------
__device__ float g_Q[(size_t)TOK * NH * HD];    // 32 MB
__device__ float g_K[(size_t)TOK * NKV * HD];   // 8 MB
__device__ float g_V[(size_t)TOK * NKV * HD];   // 8 MB
__device__ float g_AO[(size_t)TOK * NH * HD];   // 32 MB

// ================= SGEMM (NT): C[M,N] = A[M,K] * B[N,K]^T, all row-major =================
constexpr int GBM = 128, GBN = 128, GBK = 32, GTM = 8, GTN = 8;

__global__ __launch_bounds__(256, 1) void sgemm_nt(
    const float* __restrict__ A, const float* __restrict__ Bm,
    float* __restrict__ C, int M, int N, int K)
{
    __shared__ float As[GBK][GBM + 4];
    __shared__ float Bs[GBK][GBN + 4];

    const int tid = threadIdx.x;
    const int bm = blockIdx.y, bn = blockIdx.x;
    const float* Ab = A  + (size_t)bm * GBM * K;
    const float* Bb = Bm + (size_t)bn * GBN * K;

    const int lrow = tid >> 3;          // 0..31
    const int lcol = (tid & 7) << 2;    // 0,4,...,28
    const int ty = tid >> 4;            // 0..15
    const int tx = tid & 15;            // 0..15

    float acc[GTM][GTN];
#pragma unroll
    for (int i = 0; i < GTM; ++i)
#pragma unroll
        for (int j = 0; j < GTN; ++j) acc[i][j] = 0.f;

    for (int k0 = 0; k0 < K; k0 += GBK) {
#pragma unroll
        for (int r = 0; r < 4; ++r) {
            int row = lrow + r * 32;
            float4 va = *(const float4*)(Ab + (size_t)row * K + k0 + lcol);
            As[lcol + 0][row] = va.x; As[lcol + 1][row] = va.y;
            As[lcol + 2][row] = va.z; As[lcol + 3][row] = va.w;
            float4 vb = *(const float4*)(Bb + (size_t)row * K + k0 + lcol);
            Bs[lcol + 0][row] = vb.x; Bs[lcol + 1][row] = vb.y;
            Bs[lcol + 2][row] = vb.z; Bs[lcol + 3][row] = vb.w;
        }
        __syncthreads();

#pragma unroll
        for (int k = 0; k < GBK; ++k) {
            float4 a0 = *(const float4*)&As[k][ty * GTM];
            float4 a1 = *(const float4*)&As[k][ty * GTM + 4];
            float4 b0 = *(const float4*)&Bs[k][tx * GTN];
            float4 b1 = *(const float4*)&Bs[k][tx * GTN + 4];
            float a[8] = {a0.x, a0.y, a0.z, a0.w, a1.x, a1.y, a1.z, a1.w};
            float b[8] = {b0.x, b0.y, b0.z, b0.w, b1.x, b1.y, b1.z, b1.w};
#pragma unroll
            for (int i = 0; i < 8; ++i)
#pragma unroll
                for (int j = 0; j < 8; ++j) acc[i][j] += a[i] * b[j];
        }
        __syncthreads();
    }

#pragma unroll
    for (int i = 0; i < GTM; ++i) {
        size_t row = (size_t)(bm * GBM + ty * GTM + i);
        float4* cp = (float4*)(C + row * N + bn * GBN + tx * GTN);
        cp[0] = make_float4(acc[i][0], acc[i][1], acc[i][2], acc[i][3]);
        cp[1] = make_float4(acc[i][4], acc[i][5], acc[i][6], acc[i][7]);
    }
}

// ================= RoPE on Q and K (first 64 dims of each head) =================
// one thread per (token, head, d<32) pair:
//   new[d]    = x[d]*cos - x[d+32]*sin
//   new[d+32] = x[d+32]*cos + x[d]*sin
__global__ void rope_kernel()
{
    constexpr int TOTAL = TOK * (NH + NKV) * 32;
    int idx = blockIdx.x * blockDim.x + threadIdx.x;
    if (idx >= TOTAL) return;

    int d    = idx & 31;
    int r    = idx >> 5;
    int head = r % (NH + NKV);
    int tok  = r / (NH + NKV);
    int t    = tok % S_;

    // inv_freq = 10000^(-d/32); compute in double, then mimic the reference's
    // fp32 phase = fl(float(t) * float(inv_freq))
    double inv = exp(-(double)d * (9.210340371976184 / 32.0)); // ln(1e4)
    float  phase = (float)t * (float)inv;

    // robust range reduction in double (immune to fast-math sinf on large args)
    double ph = (double)phase;
    const double TWO_PI = 6.283185307179586;
    ph -= floor(ph / TWO_PI) * TWO_PI;
    float c = cosf((float)ph);
    float s = sinf((float)ph);

    float* base;
    if (head < NH) base = g_Q + (size_t)tok * (NH * HD) + head * HD;
    else           base = g_K + (size_t)tok * (NKV * HD) + (head - NH) * HD;

    float x1 = base[d];
    float x2 = base[d + 32];
    base[d]      = x1 * c - x2 * s;
    base[d + 32] = x2 * c + x1 * s;
}

// ================= sliding-window attention =================
constexpr int QT = 64, KT = 64;
constexpr int QS_STRIDE = HD + 4;   // 132 (16B-aligned rows, de-conflicted)
constexpr int PS_STRIDE = 65;       // conflict-free column access
constexpr int ATTN_SMEM_FLOATS =
    QT * QS_STRIDE + KT * QS_STRIDE + KT * HD + QT * PS_STRIDE + 3 * QT;
constexpr size_t ATTN_SMEM_BYTES = (size_t)ATTN_SMEM_FLOATS * sizeof(float);

__global__ __launch_bounds__(256, 1) void attn_kernel(
    const float* __restrict__ Q, const float* __restrict__ K,
    const float* __restrict__ V, float* __restrict__ O)
{
    extern __shared__ float smem[];
    float* Qs  = smem;                          // [QT][132]
    float* Ks  = Qs + QT * QS_STRIDE;           // [KT][132]
    float* Vs  = Ks + KT * QS_STRIDE;           // [KT][128]
    float* Ps  = Vs + KT * HD;                  // [QT][65]
    float* m_s = Ps + QT * PS_STRIDE;
    float* l_s = m_s + QT;
    float* sc_s = l_s + QT;

    const int qb = blockIdx.x, h = blockIdx.y, b = blockIdx.z;
    const int kvh = h / (NH / NKV);
    const int tid = threadIdx.x;
    const int i0 = qb * QT;

    // load Q tile
    for (int u = tid; u < QT * (HD / 4); u += 256) {
        int r = u / (HD / 4), c = (u % (HD / 4)) * 4;
        float4 v = *(const float4*)(Q + (size_t)(b * S_ + i0 + r) * (NH * HD) + h * HD + c);
        *(float4*)&Qs[r * QS_STRIDE + c] = v;
    }
    if (tid < QT) { m_s[tid] = -1e30f; l_s[tid] = 0.f; }

    const int r_own = tid & 63;     // this thread's output query row
    const int cseg  = tid >> 6;     // d segment: [cseg*32, cseg*32+32)
    float oacc[32];
#pragma unroll
    for (int j = 0; j < 32; ++j) oacc[j] = 0.f;

    const int tyq = tid >> 4;       // q micro-tile: rows tyq*4..+3
    const int txk = tid & 15;       // k micro-tile: cols txk + 16*j

    int kstart = max(0, i0 - WINDOW + 1) & ~(KT - 1);
    __syncthreads();

    for (int kb = kstart; kb <= i0; kb += KT) {
        // load K,V tiles for this key block
        for (int u = tid; u < KT * (HD / 4); u += 256) {
            int r = u / (HD / 4), c = (u % (HD / 4)) * 4;
            size_t off = (size_t)(b * S_ + kb + r) * (NKV * HD) + kvh * HD + c;
            *(float4*)&Ks[r * QS_STRIDE + c] = *(const float4*)(K + off);
            *(float4*)&Vs[r * HD + c]        = *(const float4*)(V + off);
        }
        __syncthreads();

        // S = Q K^T (64x64), each thread a 4x4 micro-tile
        float acc[4][4];
#pragma unroll
        for (int i = 0; i < 4; ++i)
#pragma unroll
            for (int j = 0; j < 4; ++j) acc[i][j] = 0.f;

        for (int d = 0; d < HD; d += 4) {
            float4 qv[4], kv[4];
#pragma unroll
            for (int i = 0; i < 4; ++i)
                qv[i] = *(const float4*)&Qs[(tyq * 4 + i) * QS_STRIDE + d];
#pragma unroll
            for (int j = 0; j < 4; ++j)
                kv[j] = *(const float4*)&Ks[(txk + 16 * j) * QS_STRIDE + d];
#pragma unroll
            for (int i = 0; i < 4; ++i)
#pragma unroll
                for (int j = 0; j < 4; ++j) {
                    acc[i][j] += qv[i].x * kv[j].x;
                    acc[i][j] += qv[i].y * kv[j].y;
                    acc[i][j] += qv[i].z * kv[j].z;
                    acc[i][j] += qv[i].w * kv[j].w;
                }
        }

        const float smul = 0.08838834764831845f;   // 1/sqrt(128)
#pragma unroll
        for (int i = 0; i < 4; ++i) {
            int qi = i0 + tyq * 4 + i;
#pragma unroll
            for (int j = 0; j < 4; ++j) {
                int kj = kb + txk + 16 * j;
                bool ok = (kj <= qi) && (kj > qi - WINDOW);
                Ps[(tyq * 4 + i) * PS_STRIDE + txk + 16 * j] =
                    ok ? acc[i][j] * smul : -1e30f;
            }
        }
        __syncthreads();

        // online softmax, one thread per query row
        if (tid < QT) {
            int r = tid;
            float mprev = m_s[r];
            float mx = mprev;
#pragma unroll 8
            for (int k2 = 0; k2 < KT; ++k2) mx = fmaxf(mx, Ps[r * PS_STRIDE + k2]);
            float corr = __expf(mprev - mx);
            float l = l_s[r] * corr;
#pragma unroll 8
            for (int k2 = 0; k2 < KT; ++k2) {
                float p = __expf(Ps[r * PS_STRIDE + k2] - mx);
                Ps[r * PS_STRIDE + k2] = p;
                l += p;
            }
            m_s[r] = mx; l_s[r] = l; sc_s[r] = corr;
        }
        __syncthreads();

        // O = corr*O + P @ V
        float corr = sc_s[r_own];
#pragma unroll
        for (int j = 0; j < 32; ++j) oacc[j] *= corr;
#pragma unroll 4
        for (int k2 = 0; k2 < KT; ++k2) {
            float p = Ps[r_own * PS_STRIDE + k2];
            const float* vrow = &Vs[k2 * HD + cseg * 32];
#pragma unroll
            for (int j = 0; j < 32; ++j) oacc[j] += p * vrow[j];
        }
        __syncthreads();
    }

    float linv = 1.0f / l_s[r_own];
    float* op = O + (size_t)(b * S_ + i0 + r_own) * (NH * HD) + h * HD + cseg * 32;
#pragma unroll
    for (int j4 = 0; j4 < 8; ++j4) {
        float4 v = make_float4(oacc[j4 * 4 + 0] * linv, oacc[j4 * 4 + 1] * linv,
                               oacc[j4 * 4 + 2] * linv, oacc[j4 * 4 + 3] * linv);
        *(float4*)(op + j4 * 4) = v;
    }
}

// ================= launch =================
extern "C" void kernel_launch(void* const* d_in, const int* in_sizes, int n_in,
                              void* d_out, int out_size)
{
    const float* X  = (const float*)d_in[0];   // [B,S,HID]
    const float* Wq = (const float*)d_in[1];   // [NH*HD, HID]
    const float* Wk = (const float*)d_in[2];   // [NKV*HD, HID]
    const float* Wv = (const float*)d_in[3];   // [NKV*HD, HID]
    const float* Wo = (const float*)d_in[4];   // [HID, NH*HD]
    float* out = (float*)d_out;

    float *q_ptr, *k_ptr, *v_ptr, *ao_ptr;
    cudaGetSymbolAddress((void**)&q_ptr,  g_Q);
    cudaGetSymbolAddress((void**)&k_ptr,  g_K);
    cudaGetSymbolAddress((void**)&v_ptr,  g_V);
    cudaGetSymbolAddress((void**)&ao_ptr, g_AO);

    // QKV projections
    {
        dim3 gq(NH * HD / GBN, TOK / GBM);      // (16, 32)
        sgemm_nt<<<gq, 256>>>(X, Wq, q_ptr, TOK, NH * HD, HID);
        dim3 gk(NKV * HD / GBN, TOK / GBM);     // (4, 32)
        sgemm_nt<<<gk, 256>>>(X, Wk, k_ptr, TOK, NKV * HD, HID);
        sgemm_nt<<<gk, 256>>>(X, Wv, v_ptr, TOK, NKV * HD, HID);
    }

    // RoPE
    {
        constexpr int TOTAL = TOK * (NH + NKV) * 32;
        rope_kernel<<<(TOTAL + 255) / 256, 256>>>();
    }

    // attention
    {
        cudaFuncSetAttribute(attn_kernel,
                             cudaFuncAttributeMaxDynamicSharedMemorySize,
                             (int)ATTN_SMEM_BYTES);
        dim3 ga(S_ / QT, NH, B_);               // (32, 16, 2)
        attn_kernel<<<ga, 256, ATTN_SMEM_BYTES>>>(q_ptr, k_ptr, v_ptr, ao_ptr);
    }

    // output projection
    {
        dim3 go(HID / GBN, TOK / GBM);          // (16, 32)
        sgemm_nt<<<go, 256>>>(ao_ptr, Wo, out, TOK, HID, HID);
    }
}

// round 7
// speedup vs baseline: 2.0449x; 2.0449x over previous
#include <cuda_runtime.h>
#include <cuda_bf16.h>
#include <math.h>
#include <cstdint>

// ---------------- problem constants ----------------
constexpr int B_   = 2;
constexpr int S_   = 2048;
constexpr int HID  = 2048;
constexpr int NH   = 16;
constexpr int NKV  = 4;
constexpr int HD   = 128;
constexpr int WINDOW = 512;
constexpr int TOK  = B_ * S_;          // 4096

// single extern dynamic-smem symbol shared by all kernels
extern __shared__ char dyn_smem[];

// ---------------- scratch (device globals; no allocation allowed) ----------------
__device__ __align__(256) float g_Q[(size_t)TOK * NH * HD];
__device__ __align__(256) float g_K[(size_t)TOK * NKV * HD];
__device__ __align__(256) float g_V[(size_t)TOK * NKV * HD];
__device__ __align__(256) float g_AO[(size_t)TOK * NH * HD];

// bf16 hi/lo splits
__device__ __align__(256) __nv_bfloat16 g_Xhi[(size_t)TOK * HID];
__device__ __align__(256) __nv_bfloat16 g_Xlo[(size_t)TOK * HID];
__device__ __align__(256) __nv_bfloat16 g_Wqhi[(size_t)NH * HD * HID];
__device__ __align__(256) __nv_bfloat16 g_Wqlo[(size_t)NH * HD * HID];
__device__ __align__(256) __nv_bfloat16 g_Wkhi[(size_t)NKV * HD * HID];
__device__ __align__(256) __nv_bfloat16 g_Wklo[(size_t)NKV * HD * HID];
__device__ __align__(256) __nv_bfloat16 g_Wvhi[(size_t)NKV * HD * HID];
__device__ __align__(256) __nv_bfloat16 g_Wvlo[(size_t)NKV * HD * HID];
__device__ __align__(256) __nv_bfloat16 g_Wohi[(size_t)HID * NH * HD];
__device__ __align__(256) __nv_bfloat16 g_Wolo[(size_t)HID * NH * HD];
__device__ __align__(256) __nv_bfloat16 g_AOhi[(size_t)TOK * NH * HD];
__device__ __align__(256) __nv_bfloat16 g_AOlo[(size_t)TOK * NH * HD];

// RoPE tables
__device__ float g_rcos[S_ * 32];
__device__ float g_rsin[S_ * 32];

// ================= PTX helpers (sm_80-level only; no tcgen05) =================
__device__ __forceinline__ uint32_t smem_u32(const void* p) {
    uint32_t a;
    asm("{ .reg .u64 t; cvta.to.shared.u64 t, %1; cvt.u32.u64 %0, t; }" : "=r"(a) : "l"(p));
    return a;
}
__device__ __forceinline__ void cp16(uint32_t dst, const void* src) {
    asm volatile("cp.async.cg.shared.global [%0], [%1], 16;" :: "r"(dst), "l"(src) : "memory");
}
#define CP_COMMIT() asm volatile("cp.async.commit_group;" ::: "memory")

__device__ __forceinline__ void ldsm_x4(uint32_t& r0, uint32_t& r1, uint32_t& r2, uint32_t& r3,
                                        uint32_t addr) {
    asm volatile("ldmatrix.sync.aligned.m8n8.x4.shared.b16 {%0,%1,%2,%3}, [%4];"
                 : "=r"(r0), "=r"(r1), "=r"(r2), "=r"(r3) : "r"(addr));
}
__device__ __forceinline__ void ldsm_x2(uint32_t& r0, uint32_t& r1, uint32_t addr) {
    asm volatile("ldmatrix.sync.aligned.m8n8.x2.shared.b16 {%0,%1}, [%2];"
                 : "=r"(r0), "=r"(r1) : "r"(addr));
}
__device__ __forceinline__ void mma_bf16(float* c, const uint32_t* a, const uint32_t* b) {
    asm volatile(
        "mma.sync.aligned.m16n8k16.row.col.f32.bf16.bf16.f32 "
        "{%0,%1,%2,%3},{%4,%5,%6,%7},{%8,%9},{%0,%1,%2,%3};"
        : "+f"(c[0]), "+f"(c[1]), "+f"(c[2]), "+f"(c[3])
        : "r"(a[0]), "r"(a[1]), "r"(a[2]), "r"(a[3]), "r"(b[0]), "r"(b[1]));
}

// ================= fp32 -> bf16 hi/lo split =================
__global__ void split_kernel(const float* __restrict__ src,
                             __nv_bfloat16* __restrict__ hi,
                             __nv_bfloat16* __restrict__ lo, int n)
{
    int i = blockIdx.x * blockDim.x + threadIdx.x;
    if (i >= n) return;
    float x = src[i];
    __nv_bfloat16 h = __float2bfloat16(x);
    float rem = x - __bfloat162float(h);
    hi[i] = h;
    lo[i] = __float2bfloat16(rem);
}

// ================= bf16x3 GEMM via mma.sync (NT): C[M,N] = A[M,K]*B[N,K]^T ======
constexpr int BM = 128, BN = 64, BK = 32;
constexpr int ROWH = 40;                 // halves per smem row (80 B stride, conflict-free)
constexpr int A_BUF_B = BM * ROWH * 2;   // 10240 B per stage
constexpr int B_BUF_B = BN * ROWH * 2;   // 5120 B per stage
constexpr int OF_AH = 0;
constexpr int OF_AL = OF_AH + 2 * A_BUF_B;
constexpr int OF_BH = OF_AL + 2 * A_BUF_B;
constexpr int OF_BL = OF_BH + 2 * B_BUF_B;
constexpr int MM_SMEM = OF_BL + 2 * B_BUF_B;   // 61440 B

__global__ __launch_bounds__(256, 2) void gemm_mma3(
    const __nv_bfloat16* __restrict__ Ahi, const __nv_bfloat16* __restrict__ Alo,
    const __nv_bfloat16* __restrict__ Bhi, const __nv_bfloat16* __restrict__ Blo,
    float* __restrict__ C, int M, int N, int K)
{
    char* smem = dyn_smem;
    const uint32_t sb = smem_u32(smem);
    const int tid  = threadIdx.x;
    const int wid  = tid >> 5;
    const int lane = tid & 31;
    const int bn = blockIdx.x, bm = blockIdx.y;

    const int m0 = (wid & 3) * 32;    // warp row start in tile
    const int n0 = (wid >> 2) * 32;   // warp col start in tile

    float acc[2][4][4];
#pragma unroll
    for (int mt = 0; mt < 2; ++mt)
#pragma unroll
        for (int nt = 0; nt < 4; ++nt)
#pragma unroll
            for (int q = 0; q < 4; ++q) acc[mt][nt][q] = 0.f;

    const int NC = K / BK;   // chunks

    auto issue_load = [&](int ch, int buf) {
        const int k0 = ch * BK;
        // A: 128 rows x 4 x16B -> 512 cp.async, 2 per thread (hi and lo each)
#pragma unroll
        for (int it = 0; it < 2; ++it) {
            int idx = tid + it * 256;
            int r = idx >> 2, c = idx & 3;
            uint32_t off = (uint32_t)((buf * BM + r) * ROWH * 2 + c * 16);
            cp16(sb + OF_AH + off, Ahi + (size_t)(bm * BM + r) * K + k0 + c * 8);
            cp16(sb + OF_AL + off, Alo + (size_t)(bm * BM + r) * K + k0 + c * 8);
        }
        // B: 64 rows x 4 x16B -> 256 cp.async, 1 per thread (hi and lo each)
        {
            int r = tid >> 2, c = tid & 3;
            uint32_t off = (uint32_t)((buf * BN + r) * ROWH * 2 + c * 16);
            cp16(sb + OF_BH + off, Bhi + (size_t)(bn * BN + r) * K + k0 + c * 8);
            cp16(sb + OF_BL + off, Blo + (size_t)(bn * BN + r) * K + k0 + c * 8);
        }
        CP_COMMIT();
    };

    issue_load(0, 0);

    const int alr = lane & 15;          // A ldmatrix row within 16
    const int alc = (lane >> 4) * 8;    // A ldmatrix col half
    const int blr = lane & 7;           // B ldmatrix row within 8
    const int blc = ((lane >> 3) & 1) * 8;

    for (int ch = 0; ch < NC; ++ch) {
        const int buf = ch & 1;
        if (ch + 1 < NC) {
            issue_load(ch + 1, (ch + 1) & 1);
            asm volatile("cp.async.wait_group 1;" ::: "memory");
        } else {
            asm volatile("cp.async.wait_group 0;" ::: "memory");
        }
        __syncthreads();

        const uint32_t aH_base = sb + OF_AH + buf * A_BUF_B;
        const uint32_t aL_base = sb + OF_AL + buf * A_BUF_B;
        const uint32_t bH_base = sb + OF_BH + buf * B_BUF_B;
        const uint32_t bL_base = sb + OF_BL + buf * B_BUF_B;

#pragma unroll
        for (int ks = 0; ks < BK; ks += 16) {
            uint32_t aH[2][4], aL[2][4], bH[4][2], bL[4][2];
#pragma unroll
            for (int mt = 0; mt < 2; ++mt) {
                uint32_t off = (uint32_t)(((m0 + mt * 16 + alr) * ROWH + ks + alc) * 2);
                ldsm_x4(aH[mt][0], aH[mt][1], aH[mt][2], aH[mt][3], aH_base + off);
                ldsm_x4(aL[mt][0], aL[mt][1], aL[mt][2], aL[mt][3], aL_base + off);
            }
#pragma unroll
            for (int nt = 0; nt < 4; ++nt) {
                uint32_t off = (uint32_t)(((n0 + nt * 8 + blr) * ROWH + ks + blc) * 2);
                ldsm_x2(bH[nt][0], bH[nt][1], bH_base + off);
                ldsm_x2(bL[nt][0], bL[nt][1], bL_base + off);
            }
#pragma unroll
            for (int mt = 0; mt < 2; ++mt)
#pragma unroll
                for (int nt = 0; nt < 4; ++nt) {
                    mma_bf16(acc[mt][nt], aH[mt], bH[nt]);
                    mma_bf16(acc[mt][nt], aH[mt], bL[nt]);
                    mma_bf16(acc[mt][nt], aL[mt], bH[nt]);
                }
        }
        __syncthreads();
    }

    // epilogue
#pragma unroll
    for (int mt = 0; mt < 2; ++mt)
#pragma unroll
        for (int nt = 0; nt < 4; ++nt) {
            int row = bm * BM + m0 + mt * 16 + (lane >> 2);
            int col = bn * BN + n0 + nt * 8 + (lane & 3) * 2;
            *(float2*)(C + (size_t)row * N + col) =
                make_float2(acc[mt][nt][0], acc[mt][nt][1]);
            *(float2*)(C + (size_t)(row + 8) * N + col) =
                make_float2(acc[mt][nt][2], acc[mt][nt][3]);
        }
}

// ================= RoPE: table then apply =================
__global__ void rope_table_kernel()
{
    int idx = blockIdx.x * blockDim.x + threadIdx.x;
    if (idx >= S_ * 32) return;
    int d = idx & 31;
    int t = idx >> 5;
    double inv = exp(-(double)d * (9.210340371976184 / 32.0));   // 10000^(-d/32)
    float phase = (float)t * (float)inv;                          // reference fp32 phase
    double ph = (double)phase;
    const double TWO_PI = 6.283185307179586;
    ph -= floor(ph / TWO_PI) * TWO_PI;
    g_rcos[idx] = cosf((float)ph);
    g_rsin[idx] = sinf((float)ph);
}

__global__ void rope_apply_kernel()
{
    constexpr int TOTAL = TOK * (NH + NKV) * 32;
    int idx = blockIdx.x * blockDim.x + threadIdx.x;
    if (idx >= TOTAL) return;

    int d    = idx & 31;
    int r    = idx >> 5;
    int head = r % (NH + NKV);
    int tok  = r / (NH + NKV);
    int t    = tok % S_;

    float c = g_rcos[t * 32 + d];
    float s = g_rsin[t * 32 + d];

    float* base;
    if (head < NH) base = g_Q + (size_t)tok * (NH * HD) + head * HD;
    else           base = g_K + (size_t)tok * (NKV * HD) + (head - NH) * HD;

    float x1 = base[d];
    float x2 = base[d + 32];
    base[d]      = x1 * c - x2 * s;
    base[d + 32] = x2 * c + x1 * s;
}

// ================= sliding-window attention =================
constexpr int QT = 64, KT = 64;
constexpr int QS_STRIDE = HD + 4;   // 132
constexpr int PS_STRIDE = 65;
constexpr int ATTN_SMEM_FLOATS =
    QT * QS_STRIDE + KT * QS_STRIDE + KT * HD + QT * PS_STRIDE + 3 * QT;
constexpr size_t ATTN_SMEM_BYTES = (size_t)ATTN_SMEM_FLOATS * sizeof(float);

__global__ __launch_bounds__(256, 1) void attn_kernel(
    const float* __restrict__ Q, const float* __restrict__ K,
    const float* __restrict__ V, float* __restrict__ O)
{
    float* smem = (float*)dyn_smem;
    float* Qs  = smem;
    float* Ks  = Qs + QT * QS_STRIDE;
    float* Vs  = Ks + KT * QS_STRIDE;
    float* Ps  = Vs + KT * HD;
    float* m_s = Ps + QT * PS_STRIDE;
    float* l_s = m_s + QT;
    float* sc_s = l_s + QT;

    const int qb = blockIdx.x, h = blockIdx.y, b = blockIdx.z;
    const int kvh = h / (NH / NKV);
    const int tid = threadIdx.x;
    const int i0 = qb * QT;

    for (int u = tid; u < QT * (HD / 4); u += 256) {
        int r = u / (HD / 4), c = (u % (HD / 4)) * 4;
        float4 v = *(const float4*)(Q + (size_t)(b * S_ + i0 + r) * (NH * HD) + h * HD + c);
        *(float4*)&Qs[r * QS_STRIDE + c] = v;
    }
    if (tid < QT) { m_s[tid] = -1e30f; l_s[tid] = 0.f; }

    const int r_own = tid & 63;
    const int cseg  = tid >> 6;
    float oacc[32];
#pragma unroll
    for (int j = 0; j < 32; ++j) oacc[j] = 0.f;

    const int tyq = tid >> 4;
    const int txk = tid & 15;

    int kstart = max(0, i0 - WINDOW + 1) & ~(KT - 1);
    __syncthreads();

    for (int kb = kstart; kb <= i0; kb += KT) {
        for (int u = tid; u < KT * (HD / 4); u += 256) {
            int r = u / (HD / 4), c = (u % (HD / 4)) * 4;
            size_t off = (size_t)(b * S_ + kb + r) * (NKV * HD) + kvh * HD + c;
            *(float4*)&Ks[r * QS_STRIDE + c] = *(const float4*)(K + off);
            *(float4*)&Vs[r * HD + c]        = *(const float4*)(V + off);
        }
        __syncthreads();

        float acc[4][4];
#pragma unroll
        for (int i = 0; i < 4; ++i)
#pragma unroll
            for (int j = 0; j < 4; ++j) acc[i][j] = 0.f;

        for (int d = 0; d < HD; d += 4) {
            float4 qv[4], kv[4];
#pragma unroll
            for (int i = 0; i < 4; ++i)
                qv[i] = *(const float4*)&Qs[(tyq * 4 + i) * QS_STRIDE + d];
#pragma unroll
            for (int j = 0; j < 4; ++j)
                kv[j] = *(const float4*)&Ks[(txk + 16 * j) * QS_STRIDE + d];
#pragma unroll
            for (int i = 0; i < 4; ++i)
#pragma unroll
                for (int j = 0; j < 4; ++j) {
                    acc[i][j] += qv[i].x * kv[j].x;
                    acc[i][j] += qv[i].y * kv[j].y;
                    acc[i][j] += qv[i].z * kv[j].z;
                    acc[i][j] += qv[i].w * kv[j].w;
                }
        }

        const float smul = 0.08838834764831845f;
#pragma unroll
        for (int i = 0; i < 4; ++i) {
            int qi = i0 + tyq * 4 + i;
#pragma unroll
            for (int j = 0; j < 4; ++j) {
                int kj = kb + txk + 16 * j;
                bool ok = (kj <= qi) && (kj > qi - WINDOW);
                Ps[(tyq * 4 + i) * PS_STRIDE + txk + 16 * j] =
                    ok ? acc[i][j] * smul : -1e30f;
            }
        }
        __syncthreads();

        if (tid < QT) {
            int r = tid;
            float mprev = m_s[r];
            float mx = mprev;
#pragma unroll 8
            for (int k2 = 0; k2 < KT; ++k2) mx = fmaxf(mx, Ps[r * PS_STRIDE + k2]);
            float corr = __expf(mprev - mx);
            float l = l_s[r] * corr;
#pragma unroll 8
            for (int k2 = 0; k2 < KT; ++k2) {
                float p = __expf(Ps[r * PS_STRIDE + k2] - mx);
                Ps[r * PS_STRIDE + k2] = p;
                l += p;
            }
            m_s[r] = mx; l_s[r] = l; sc_s[r] = corr;
        }
        __syncthreads();

        float corr = sc_s[r_own];
#pragma unroll
        for (int j = 0; j < 32; ++j) oacc[j] *= corr;
#pragma unroll 4
        for (int k2 = 0; k2 < KT; ++k2) {
            float p = Ps[r_own * PS_STRIDE + k2];
            const float* vrow = &Vs[k2 * HD + cseg * 32];
#pragma unroll
            for (int j = 0; j < 32; ++j) oacc[j] += p * vrow[j];
        }
        __syncthreads();
    }

    float linv = 1.0f / l_s[r_own];
    float* op = O + (size_t)(b * S_ + i0 + r_own) * (NH * HD) + h * HD + cseg * 32;
#pragma unroll
    for (int j4 = 0; j4 < 8; ++j4) {
        float4 v = make_float4(oacc[j4 * 4 + 0] * linv, oacc[j4 * 4 + 1] * linv,
                               oacc[j4 * 4 + 2] * linv, oacc[j4 * 4 + 3] * linv);
        *(float4*)(op + j4 * 4) = v;
    }
}

// ================= launch =================
extern "C" void kernel_launch(void* const* d_in, const int* in_sizes, int n_in,
                              void* d_out, int out_size)
{
    const float* X  = (const float*)d_in[0];   // [B,S,HID]
    const float* Wq = (const float*)d_in[1];   // [NH*HD, HID]
    const float* Wk = (const float*)d_in[2];   // [NKV*HD, HID]
    const float* Wv = (const float*)d_in[3];   // [NKV*HD, HID]
    const float* Wo = (const float*)d_in[4];   // [HID, NH*HD]
    float* out = (float*)d_out;

    float *q_ptr, *k_ptr, *v_ptr, *ao_ptr;
    cudaGetSymbolAddress((void**)&q_ptr,  g_Q);
    cudaGetSymbolAddress((void**)&k_ptr,  g_K);
    cudaGetSymbolAddress((void**)&v_ptr,  g_V);
    cudaGetSymbolAddress((void**)&ao_ptr, g_AO);

    __nv_bfloat16 *xhi, *xlo, *wqh, *wql, *wkh, *wkl, *wvh, *wvl, *woh, *wol, *aoh, *aol;
    cudaGetSymbolAddress((void**)&xhi, g_Xhi);  cudaGetSymbolAddress((void**)&xlo, g_Xlo);
    cudaGetSymbolAddress((void**)&wqh, g_Wqhi); cudaGetSymbolAddress((void**)&wql, g_Wqlo);
    cudaGetSymbolAddress((void**)&wkh, g_Wkhi); cudaGetSymbolAddress((void**)&wkl, g_Wklo);
    cudaGetSymbolAddress((void**)&wvh, g_Wvhi); cudaGetSymbolAddress((void**)&wvl, g_Wvlo);
    cudaGetSymbolAddress((void**)&woh, g_Wohi); cudaGetSymbolAddress((void**)&wol, g_Wolo);
    cudaGetSymbolAddress((void**)&aoh, g_AOhi); cudaGetSymbolAddress((void**)&aol, g_AOlo);

    auto split = [&](const float* s, __nv_bfloat16* h, __nv_bfloat16* l, int n) {
        split_kernel<<<(n + 255) / 256, 256>>>(s, h, l, n);
    };

    // bf16 hi/lo splits of inputs
    split(X,  xhi, xlo, TOK * HID);
    split(Wq, wqh, wql, NH * HD * HID);
    split(Wk, wkh, wkl, NKV * HD * HID);
    split(Wv, wvh, wvl, NKV * HD * HID);
    split(Wo, woh, wol, HID * NH * HD);

    // RoPE table
    rope_table_kernel<<<(S_ * 32 + 255) / 256, 256>>>();

    cudaFuncSetAttribute(gemm_mma3, cudaFuncAttributeMaxDynamicSharedMemorySize, MM_SMEM);

    // QKV projections on tensor cores (mma.sync bf16 x3)
    {
        dim3 gq(NH * HD / BN, TOK / BM);        // (32, 32)
        gemm_mma3<<<gq, 256, MM_SMEM>>>(xhi, xlo, wqh, wql, q_ptr, TOK, NH * HD, HID);
        dim3 gk(NKV * HD / BN, TOK / BM);       // (8, 32)
        gemm_mma3<<<gk, 256, MM_SMEM>>>(xhi, xlo, wkh, wkl, k_ptr, TOK, NKV * HD, HID);
        gemm_mma3<<<gk, 256, MM_SMEM>>>(xhi, xlo, wvh, wvl, v_ptr, TOK, NKV * HD, HID);
    }

    // RoPE apply
    {
        constexpr int TOTAL = TOK * (NH + NKV) * 32;
        rope_apply_kernel<<<(TOTAL + 255) / 256, 256>>>();
    }

    // attention
    {
        cudaFuncSetAttribute(attn_kernel,
                             cudaFuncAttributeMaxDynamicSharedMemorySize,
                             (int)ATTN_SMEM_BYTES);
        dim3 ga(S_ / QT, NH, B_);               // (32, 16, 2)
        attn_kernel<<<ga, 256, ATTN_SMEM_BYTES>>>(q_ptr, k_ptr, v_ptr, ao_ptr);
    }

    // output projection on tensor cores
    {
        split(ao_ptr, aoh, aol, TOK * NH * HD);
        dim3 go(HID / BN, TOK / BM);            // (32, 32)
        gemm_mma3<<<go, 256, MM_SMEM>>>(aoh, aol, woh, wol, out, TOK, HID, HID);
    }
}